// round 2
// baseline (speedup 1.0000x reference)
#include <cuda_runtime.h>
#include <stdint.h>

#define P1 2654435761u
#define P2 805459861u

// 16 lanes per point: lane = corner(3 bits) << 1 | half(1 bit).
// Lane pair (2c, 2c+1) loads the two 16B halves of corner c's 32B feature row
// -> same 128B line -> single L1tex wavefront (vs 2 in the per-thread version).
template <bool POW2>
__global__ __launch_bounds__(256)
void hash_interp_lanes(const float* __restrict__ pts,
                       const float* __restrict__ feat,
                       float* __restrict__ out,
                       int n, unsigned buckets, unsigned mask)
{
    const unsigned lane = threadIdx.x & 31u;
    const int gwarp = (int)((blockIdx.x * blockDim.x + threadIdx.x) >> 5);

    const int p_raw = gwarp * 2 + (int)(lane >> 4);   // 2 points per warp
    const bool valid = (p_raw < n);
    const int p = valid ? p_raw : 0;

    const unsigned sub = lane & 15u;
    const unsigned c   = sub >> 1;       // corner 0..7 (x-fastest order)
    const unsigned h   = sub & 1u;       // which 16B half of the feature row
    const unsigned cx = c & 1u;
    const unsigned cy = (c >> 1) & 1u;
    const unsigned cz = (c >> 2) & 1u;

    // point coords (broadcast loads within each 16-lane group)
    const float px = __ldg(pts + 3 * (size_t)p + 0);
    const float py = __ldg(pts + 3 * (size_t)p + 1);
    const float pz = __ldg(pts + 3 * (size_t)p + 2);

    // continuous grid coords, matching reference's pts / 0.005
    const float qx = px / 0.005f;
    const float qy = py / 0.005f;
    const float qz = pz / 0.005f;

    const float bxf = floorf(qx);
    const float byf = floorf(qy);
    const float bzf = floorf(qz);
    const int bx = (int)bxf, by = (int)byf, bz = (int)bzf;

    const float fx = qx - bxf;
    const float fy = qy - byf;
    const float fz = qz - bzf;

    // per-lane corner hash
    const unsigned hx = (unsigned)(bx + (int)cx);                 // * 1
    const unsigned hy = ((unsigned)by + cy) * P1;
    const unsigned hz = ((unsigned)bz + cz) * P2;
    const unsigned hsh = hx ^ hy ^ hz;
    const unsigned slot = POW2 ? (hsh & mask) : (hsh % buckets);

    // trilinear weight for this corner (same mult order as reference prod)
    const float wx = cx ? fx : (1.0f - fx);
    const float wy = cy ? fy : (1.0f - fy);
    const float wz = cz ? fz : (1.0f - fz);
    const float w = wx * wy * wz;

    // single 16B gather per lane; pair-lanes share the 128B line
    float4 v = __ldg(reinterpret_cast<const float4*>(feat) + ((size_t)slot * 2 + h));
    v.x *= w; v.y *= w; v.z *= w; v.w *= w;

    // butterfly-reduce over the 8 corners: xor masks 2,4,8 keep half-parity
    // (bit 0) and point id (bit 4) separate.
#pragma unroll
    for (int m = 2; m <= 8; m <<= 1) {
        v.x += __shfl_xor_sync(0xffffffffu, v.x, m);
        v.y += __shfl_xor_sync(0xffffffffu, v.y, m);
        v.z += __shfl_xor_sync(0xffffffffu, v.z, m);
        v.w += __shfl_xor_sync(0xffffffffu, v.w, m);
    }

    if (valid && c == 0) {
        reinterpret_cast<float4*>(out + (size_t)p_raw * 8)[h] = v;
    }
}

extern "C" void kernel_launch(void* const* d_in, const int* in_sizes, int n_in,
                              void* d_out, int out_size)
{
    const float* pts  = (const float*)d_in[0];
    const float* feat = (const float*)d_in[1];
    float* out = (float*)d_out;

    int n = in_sizes[0] / 3;
    unsigned buckets = (unsigned)(in_sizes[1] / 8);
    unsigned mask = buckets - 1u;
    bool pow2 = (buckets & (buckets - 1u)) == 0u;

    // 16 lanes per point -> total threads = 16*n (2 points per warp)
    long long warps = ((long long)n + 1) / 2;
    long long threads_total = warps * 32;
    int threads = 256;
    int blocks = (int)((threads_total + threads - 1) / threads);

    if (pow2) {
        hash_interp_lanes<true><<<blocks, threads>>>(pts, feat, out, n, buckets, mask);
    } else {
        hash_interp_lanes<false><<<blocks, threads>>>(pts, feat, out, n, buckets, mask);
    }
}

// round 3
// speedup vs baseline: 2.0675x; 2.0675x over previous
#include <cuda_runtime.h>
#include <stdint.h>

#define P1 2654435761u
#define P2 805459861u

// 2 lanes per point: lane 2k+h handles point (warp_base + k), half h of the
// 32B feature row. In each gather instruction, lanes 2k/2k+1 hit the SAME
// 128B line (lo/hi halves of one slot) -> 1 L1tex wavefront per corner per
// point (8 wf/pt) instead of 16, with only 2x ALU setup redundancy and no
// cross-lane reduction.
template <bool POW2>
__global__ __launch_bounds__(256)
void hash_interp_half(const float* __restrict__ pts,
                      const float* __restrict__ feat,
                      float* __restrict__ out,
                      int n, unsigned buckets, unsigned mask)
{
    const unsigned lane = threadIdx.x & 31u;
    const int gwarp = (int)((blockIdx.x * blockDim.x + threadIdx.x) >> 5);

    const int p_raw = gwarp * 16 + (int)(lane >> 1);   // 16 points per warp
    const bool valid = (p_raw < n);
    const int p = valid ? p_raw : 0;
    const unsigned h = lane & 1u;                      // 16B half of the row

    // point coords (pair-lanes read identical addresses -> broadcast)
    const float px = __ldg(pts + 3 * (size_t)p + 0);
    const float py = __ldg(pts + 3 * (size_t)p + 1);
    const float pz = __ldg(pts + 3 * (size_t)p + 2);

    // continuous grid coords, matching reference's pts / 0.005
    const float qx = px / 0.005f;
    const float qy = py / 0.005f;
    const float qz = pz / 0.005f;

    const float bxf = floorf(qx);
    const float byf = floorf(qy);
    const float bzf = floorf(qz);
    const int bx = (int)bxf, by = (int)byf, bz = (int)bzf;

    const float fx = qx - bxf;
    const float fy = qy - byf;
    const float fz = qz - bzf;

    // per-axis hash terms
    const unsigned hx0 = (unsigned)bx;           // * 1
    const unsigned hx1 = (unsigned)(bx + 1);
    const unsigned hy0 = (unsigned)by * P1;
    const unsigned hy1 = hy0 + P1;
    const unsigned hz0 = (unsigned)bz * P2;
    const unsigned hz1 = hz0 + P2;

    unsigned slot[8];
    {
        const unsigned s0 = hx0 ^ hy0 ^ hz0;
        const unsigned s1 = hx1 ^ hy0 ^ hz0;
        const unsigned s2 = hx0 ^ hy1 ^ hz0;
        const unsigned s3 = hx1 ^ hy1 ^ hz0;
        const unsigned s4 = hx0 ^ hy0 ^ hz1;
        const unsigned s5 = hx1 ^ hy0 ^ hz1;
        const unsigned s6 = hx0 ^ hy1 ^ hz1;
        const unsigned s7 = hx1 ^ hy1 ^ hz1;
        if (POW2) {
            slot[0] = s0 & mask; slot[1] = s1 & mask; slot[2] = s2 & mask; slot[3] = s3 & mask;
            slot[4] = s4 & mask; slot[5] = s5 & mask; slot[6] = s6 & mask; slot[7] = s7 & mask;
        } else {
            slot[0] = s0 % buckets; slot[1] = s1 % buckets; slot[2] = s2 % buckets; slot[3] = s3 % buckets;
            slot[4] = s4 % buckets; slot[5] = s5 % buckets; slot[6] = s6 % buckets; slot[7] = s7 % buckets;
        }
    }

    // trilinear weights (same multiply order as reference)
    const float wx0 = 1.0f - fx, wx1 = fx;
    const float wy0 = 1.0f - fy, wy1 = fy;
    const float wz0 = 1.0f - fz, wz1 = fz;
    float w[8];
    w[0] = wx0 * wy0 * wz0;
    w[1] = wx1 * wy0 * wz0;
    w[2] = wx0 * wy1 * wz0;
    w[3] = wx1 * wy1 * wz0;
    w[4] = wx0 * wy0 * wz1;
    w[5] = wx1 * wy0 * wz1;
    w[6] = wx0 * wy1 * wz1;
    w[7] = wx1 * wy1 * wz1;

    // issue all 8 gathers up-front for MLP; pair-lanes share each 128B line
    const float4* fbase = reinterpret_cast<const float4*>(feat);
    float4 v[8];
#pragma unroll
    for (int c = 0; c < 8; c++) {
        v[c] = __ldg(fbase + ((size_t)slot[c] * 2 + h));
    }

    float a0 = 0.f, a1 = 0.f, a2 = 0.f, a3 = 0.f;
#pragma unroll
    for (int c = 0; c < 8; c++) {
        const float wc = w[c];
        a0 = fmaf(wc, v[c].x, a0);
        a1 = fmaf(wc, v[c].y, a1);
        a2 = fmaf(wc, v[c].z, a2);
        a3 = fmaf(wc, v[c].w, a3);
    }

    if (valid) {
        // lane 2k -> float4 index 2p, lane 2k+1 -> 2p+1: fully coalesced
        reinterpret_cast<float4*>(out)[(size_t)p_raw * 2 + h] =
            make_float4(a0, a1, a2, a3);
    }
}

extern "C" void kernel_launch(void* const* d_in, const int* in_sizes, int n_in,
                              void* d_out, int out_size)
{
    const float* pts  = (const float*)d_in[0];
    const float* feat = (const float*)d_in[1];
    float* out = (float*)d_out;

    int n = in_sizes[0] / 3;
    unsigned buckets = (unsigned)(in_sizes[1] / 8);
    unsigned mask = buckets - 1u;
    bool pow2 = (buckets & (buckets - 1u)) == 0u;

    // 2 lanes per point -> 16 points per warp
    long long warps = ((long long)n + 15) / 16;
    long long threads_total = warps * 32;
    int threads = 256;
    int blocks = (int)((threads_total + threads - 1) / threads);

    if (pow2) {
        hash_interp_half<true><<<blocks, threads>>>(pts, feat, out, n, buckets, mask);
    } else {
        hash_interp_half<false><<<blocks, threads>>>(pts, feat, out, n, buckets, mask);
    }
}